// round 13
// baseline (speedup 1.0000x reference)
#include <cuda_runtime.h>
#include <cuda_fp16.h>
#include <cstdint>
#include <cstddef>

#define V_   512
#define L_   13
#define L16  16
#define NC   2048            // B*C = 64*32
#define NCOL 32768           // NC*L16 (padded Y layout)
#define ND   26624           // NC*13 dense column count
#define COUT 64
#define KCAT 224
#define NB   64              // batch

// ------------------------- scratch (device globals; no allocs) -------------
__device__ __align__(16) __half g_Ah[6 * V_ * V_];   // [k][v][w] fp16: A0,A0^2,A1,A1^2,A2,A2^2
__device__ __align__(16) __half g_Xh[(size_t)NC * V_ * L16];     // [nc][v][l16], l=13..15 zero (gemm_out)
__device__ __align__(16) __half g_Xd[(size_t)V_ * ND];           // [v][j], j=nc*13+l dense (gemm_prop)
__device__ __align__(16) __half g_Yh[(size_t)6 * V_ * NC * L16]; // [k][w][nc*16+l]; pad cols stay 0
__device__ __align__(16) __half g_Wt[KCAT * COUT];               // [kc][o]

// ------------------------- PTX helpers ------------------------------------
__device__ __forceinline__ uint32_t smem_u32(const void* p) {
    return (uint32_t)__cvta_generic_to_shared(p);
}
__device__ __forceinline__ void cpasync16(uint32_t dst, const void* src) {
    asm volatile("cp.async.cg.shared.global [%0], [%1], 16;\n" :: "r"(dst), "l"(src));
}
__device__ __forceinline__ void cpcommit() { asm volatile("cp.async.commit_group;\n" ::: "memory"); }
template <int N>
__device__ __forceinline__ void cpwait() { asm volatile("cp.async.wait_group %0;\n" :: "n"(N) : "memory"); }

// A fragment (row-major m16k16) from SMEM stored [k][m], via x4 .trans
__device__ __forceinline__ void ldmA(uint32_t a[4], uint32_t addr) {
    asm volatile("ldmatrix.sync.aligned.m8n8.x4.trans.shared.b16 {%0,%1,%2,%3}, [%4];\n"
                 : "=r"(a[0]), "=r"(a[1]), "=r"(a[2]), "=r"(a[3]) : "r"(addr));
}
// B fragment (col-major k16n8) from SMEM stored [k][n], via x2 .trans
__device__ __forceinline__ void ldmB(uint32_t b[2], uint32_t addr) {
    asm volatile("ldmatrix.sync.aligned.m8n8.x2.trans.shared.b16 {%0,%1}, [%2];\n"
                 : "=r"(b[0]), "=r"(b[1]) : "r"(addr));
}
__device__ __forceinline__ void mma16816(float c[4], const uint32_t a[4], const uint32_t b[2]) {
    asm volatile("mma.sync.aligned.m16n8k16.row.col.f32.f16.f16.f32 "
                 "{%0,%1,%2,%3}, {%4,%5,%6,%7}, {%8,%9}, {%0,%1,%2,%3};\n"
                 : "+f"(c[0]), "+f"(c[1]), "+f"(c[2]), "+f"(c[3])
                 : "r"(a[0]), "r"(a[1]), "r"(a[2]), "r"(a[3]), "r"(b[0]), "r"(b[1]));
}

// ------------------------- prep kernels ------------------------------------
// A_j @ A_j, fp32 accumulate, fp16 straight into g_Ah odd slots (layout [i][w])
__global__ __launch_bounds__(1024) void sq_kernel(const float* __restrict__ s0,
                                                  const float* __restrict__ s1,
                                                  const float* __restrict__ s2) {
    const float* A = (blockIdx.z == 0) ? s0 : (blockIdx.z == 1) ? s1 : s2;
    __half* O = g_Ah + (size_t)(2 * blockIdx.z + 1) * V_ * V_;
    __shared__ float a[32][33], bsh[32][33];
    int tx = threadIdx.x, ty = threadIdx.y;
    int i = blockIdx.y * 32 + ty;
    int w = blockIdx.x * 32 + tx;
    float acc = 0.f;
    for (int kt = 0; kt < 16; kt++) {
        a[ty][tx]   = A[i * V_ + kt * 32 + tx];
        bsh[ty][tx] = A[(kt * 32 + ty) * V_ + w];
        __syncthreads();
#pragma unroll
        for (int kk = 0; kk < 32; kk++) acc += a[ty][kk] * bsh[kk][tx];
        __syncthreads();
    }
    O[i * V_ + w] = __float2half(acc);
}

// fp32 -> fp16 copy of supports into even slots (float4 loads)
__global__ __launch_bounds__(256) void quant_A(const float* __restrict__ s0,
                                               const float* __restrict__ s1,
                                               const float* __restrict__ s2) {
    int i = blockIdx.x * 256 + threadIdx.x;   // over 65536 = (512*512)/4
    const float* srcs[3] = {s0, s1, s2};
#pragma unroll
    for (int j = 0; j < 3; j++) {
        float4 v = ((const float4*)srcs[j])[i];
        __half2* d = (__half2*)(g_Ah + (size_t)(2 * j) * V_ * V_ + (size_t)i * 4);
        d[0] = __floats2half2_rn(v.x, v.y);
        d[1] = __floats2half2_rn(v.z, v.w);
    }
}

// x [nc][v][13] fp32 -> g_Xh [nc][v][16] (padded) AND g_Xd [v][nc*13+l] (dense)
__global__ __launch_bounds__(256) void repack_both(const float* __restrict__ x) {
    int nc = blockIdx.x, tid = threadIdx.x;
    const float* src = x + (size_t)nc * V_ * L_;
    __half* xh = g_Xh + (size_t)nc * V_ * L16;
    for (int idx = tid; idx < V_ * L_; idx += 256) {
        int v = idx / L_, l = idx - v * L_;
        __half h = __float2half(src[idx]);
        xh[v * L16 + l] = h;
        g_Xd[(size_t)v * ND + nc * L_ + l] = h;
    }
    for (int v = tid; v < V_; v += 256) {
        xh[v * L16 + 13] = __half(0.f);
        xh[v * L16 + 14] = __half(0.f);
        xh[v * L16 + 15] = __half(0.f);
    }
}

__global__ __launch_bounds__(256) void conv_W(const float* __restrict__ W) {
    int t = blockIdx.x * 256 + threadIdx.x;   // 14336 = 56*256
    int o = t / KCAT, kc = t % KCAT;
    g_Wt[kc * COUT + o] = __float2half(W[t]);
}

// ------------------------- GEMM 1: propagations (dense N) ------------------
// Y_k[w][j] = sum_v P_k[v][w] * Xd[v][j],  M=512(w), K=512(v), N=26624(j dense)
// BM=128, BN=128, BK=32; 8 warps 2(M) x 4(N); warp tile 64x32
// 3-stage cp.async, single __syncthreads per k-tile, 2 CTAs/SM.
// Epilogue scatters dense j -> padded Y column nc*16+l.
#define PROP_SA   (32 * 136)          // halfs, A tile per stage
#define PROP_SS   (2 * PROP_SA)       // halfs per stage (A + B)
#define PROP_SMEM (3 * PROP_SS * 2)   // 52224 bytes

__global__ void __launch_bounds__(256, 2) gemm_prop() {
    extern __shared__ __half sm[];
    int tid = threadIdx.x;
    int lane = tid & 31, wid = tid >> 5;
    int warp_m = wid >> 2;              // 0..1
    int warp_n = wid & 3;               // 0..3
    int w0 = blockIdx.y * 128;
    int j0 = blockIdx.x * 128;          // dense column base
    int k6 = blockIdx.z;
    const __half* Abase = g_Ah + (size_t)k6 * V_ * V_;

    auto load_tiles = [&](int kt, int s) {
        __half* As = sm + s * PROP_SS;
        __half* Bs = As + PROP_SA;
        int v0 = kt * 32;
#pragma unroll
        for (int i = 0; i < 2; i++) {
            int ch = tid + i * 256;                 // 512 chunks of 16B
            int r = ch >> 4, c16 = ch & 15;
            cpasync16(smem_u32(As + r * 136 + c16 * 8),
                      Abase + (size_t)(v0 + r) * V_ + w0 + c16 * 8);
        }
#pragma unroll
        for (int i = 0; i < 2; i++) {
            int ch = tid + i * 256;                 // B rows fully contiguous now
            int r = ch >> 4, c16 = ch & 15;
            cpasync16(smem_u32(Bs + r * 136 + c16 * 8),
                      g_Xd + (size_t)(v0 + r) * ND + j0 + c16 * 8);
        }
    };

    float acc[4][4][4] = {};

    load_tiles(0, 0); cpcommit();
    load_tiles(1, 1); cpcommit();

    for (int kt = 0; kt < 16; kt++) {
        cpwait<1>();
        __syncthreads();                 // tile kt resident; all warps done with kt-1
        if (kt + 2 < 16) load_tiles(kt + 2, (kt + 2) % 3);
        cpcommit();
        __half* As = sm + (kt % 3) * PROP_SS;
        __half* Bs = As + PROP_SA;
#pragma unroll
        for (int ks = 0; ks < 2; ks++) {
            uint32_t af[4][4], bf[4][2];
            int arow = ks * 16 + (lane & 7) + ((lane & 16) >> 1);
            int acolb = warp_m * 64 + (lane & 8);
#pragma unroll
            for (int mt = 0; mt < 4; mt++)
                ldmA(af[mt], smem_u32(As + arow * 136 + acolb + mt * 16));
            int brow = ks * 16 + (lane & 15);
            int bcolb = warp_n * 32;
#pragma unroll
            for (int nt = 0; nt < 4; nt++)
                ldmB(bf[nt], smem_u32(Bs + brow * 136 + bcolb + nt * 8));
#pragma unroll
            for (int mt = 0; mt < 4; mt++)
#pragma unroll
                for (int nt = 0; nt < 4; nt++)
                    mma16816(acc[mt][nt], af[mt], bf[nt]);
        }
    }

    // epilogue: scatter dense j -> padded Y[w][nc*16+l] (pad cols untouched = 0)
    int g = lane >> 2, t4 = lane & 3;
    __half* Ybase = g_Yh + (size_t)k6 * V_ * NCOL;
#pragma unroll
    for (int mt = 0; mt < 4; mt++) {
        int w = w0 + warp_m * 64 + mt * 16 + g;
        __half* row0 = Ybase + (size_t)w * NCOL;
        __half* row1 = row0 + (size_t)8 * NCOL;
#pragma unroll
        for (int nt = 0; nt < 4; nt++) {
            int j = j0 + warp_n * 32 + nt * 8 + 2 * t4;
            int nc_a = j / 13,      l_a = j - nc_a * 13;
            int nc_b = (j + 1) / 13, l_b = (j + 1) - nc_b * 13;
            int ca = nc_a * 16 + l_a, cb = nc_b * 16 + l_b;
            row0[ca] = __float2half(acc[mt][nt][0]);
            row0[cb] = __float2half(acc[mt][nt][1]);
            row1[ca] = __float2half(acc[mt][nt][2]);
            row1[cb] = __float2half(acc[mt][nt][3]);
        }
    }
}

// ------------------------- GEMM 2: 1x1 conv over 224 channels --------------
// out[n][o][v][l] = b[o] + sum_kc Wt[kc][o] * H[kc][(v,l)]
// M=64(o), K=224, per-n N=8192 (v,l16); CTA: n x 8 v's (BN=128 cols)
// 3-stage pipeline over 7 k-blocks, 2 CTAs/SM.
__global__ void __launch_bounds__(256, 2) gemm_out(const float* __restrict__ bias,
                                                   float* __restrict__ out) {
    __shared__ __half Ws[3][32][72];    // +8 pad (144B = 9*16B)
    __shared__ __half Bs[3][32][136];   // +8 pad (272B = 17*16B)
    int tid = threadIdx.x;
    int lane = tid & 31, wid = tid >> 5;
    int warp_m = wid >> 2;              // 0..1 (32 o each)
    int warp_n = wid & 3;               // 0..3 (32 cols each)
    int n  = blockIdx.y;
    int v0 = blockIdx.x * 8;

    auto load_tiles = [&](int kb, int s) {
        {   // W chunk: 32 rows x 64 halfs = 256 chunks
            int r = tid >> 3, c16 = tid & 7;
            cpasync16(smem_u32(&Ws[s][r][c16 * 8]),
                      g_Wt + (size_t)(kb * 32 + r) * COUT + c16 * 8);
        }
        if (kb == 0) {  // x block from Xh
#pragma unroll
            for (int i = 0; i < 2; i++) {
                int ch = tid + i * 256;
                int r = ch >> 4, c16 = ch & 15;
                cpasync16(smem_u32(&Bs[s][r][c16 * 8]),
                          g_Xh + (size_t)(n * 32 + r) * (V_ * L16) + v0 * L16 + c16 * 8);
            }
        } else {        // Y block k = kb-1
            int k = kb - 1;
#pragma unroll
            for (int i = 0; i < 2; i++) {
                int ch = tid + i * 256;
                int r = ch >> 4, seg = (ch >> 1) & 7, h8 = ch & 1;
                cpasync16(smem_u32(&Bs[s][r][seg * 16 + h8 * 8]),
                          g_Yh + (size_t)(k * V_ + v0 + seg) * NCOL
                                + (n * 32 + r) * L16 + h8 * 8);
            }
        }
    };

    float acc[2][4][4] = {};

    load_tiles(0, 0); cpcommit();
    load_tiles(1, 1); cpcommit();

    for (int kb = 0; kb < 7; kb++) {
        cpwait<1>();
        __syncthreads();
        if (kb + 2 < 7) load_tiles(kb + 2, (kb + 2) % 3);
        cpcommit();
        int s = kb % 3;
#pragma unroll
        for (int ks = 0; ks < 2; ks++) {
            uint32_t af[2][4], bf[4][2];
            int arow = ks * 16 + (lane & 7) + ((lane & 16) >> 1);
            int acolb = warp_m * 32 + (lane & 8);
#pragma unroll
            for (int mt = 0; mt < 2; mt++)
                ldmA(af[mt], smem_u32(&Ws[s][arow][acolb + mt * 16]));
            int brow = ks * 16 + (lane & 15);
            int bcolb = warp_n * 32;
#pragma unroll
            for (int nt = 0; nt < 4; nt++)
                ldmB(bf[nt], smem_u32(&Bs[s][brow][bcolb + nt * 8]));
#pragma unroll
            for (int mt = 0; mt < 2; mt++)
#pragma unroll
                for (int nt = 0; nt < 4; nt++)
                    mma16816(acc[mt][nt], af[mt], bf[nt]);
        }
    }

    // epilogue: +bias, masked store (l < 13), out[n][o][v][l] fp32
    int g = lane >> 2, t = lane & 3;
#pragma unroll
    for (int mt = 0; mt < 2; mt++) {
        int o = warp_m * 32 + mt * 16 + g;
        float b0 = bias[o], b1 = bias[o + 8];
#pragma unroll
        for (int nt = 0; nt < 4; nt++) {
            int col = warp_n * 32 + nt * 8 + 2 * t;
            int v = v0 + (col >> 4);
            int l = col & 15;
            float* p = out + ((size_t)(n * COUT + o) * V_ + v) * L_ + l;
            float* q = out + ((size_t)(n * COUT + o + 8) * V_ + v) * L_ + l;
            if (l < 13)     { p[0] = acc[mt][nt][0] + b0; q[0] = acc[mt][nt][2] + b1; }
            if (l + 1 < 13) { p[1] = acc[mt][nt][1] + b0; q[1] = acc[mt][nt][3] + b1; }
        }
    }
}

// ------------------------- launch ------------------------------------------
extern "C" void kernel_launch(void* const* d_in, const int* in_sizes, int n_in,
                              void* d_out, int out_size) {
    const float* x  = (const float*)d_in[0];
    const float* s0 = (const float*)d_in[1];
    const float* s1 = (const float*)d_in[2];
    const float* s2 = (const float*)d_in[3];
    const float* W  = (const float*)d_in[4];
    const float* b  = (const float*)d_in[5];
    float* out = (float*)d_out;
    (void)in_sizes; (void)n_in; (void)out_size;

    static bool attr_done = false;
    if (!attr_done) {
        cudaFuncSetAttribute(gemm_prop, cudaFuncAttributeMaxDynamicSharedMemorySize, PROP_SMEM);
        attr_done = true;
    }

    sq_kernel<<<dim3(16, 16, 3), dim3(32, 32)>>>(s0, s1, s2);
    quant_A<<<256, 256>>>(s0, s1, s2);
    repack_both<<<NC, 256>>>(x);
    conv_W<<<56, 256>>>(W);
    gemm_prop<<<dim3(208, 4, 6), 256, PROP_SMEM>>>();
    gemm_out<<<dim3(64, 64), 256>>>(b, out);
}

// round 14
// speedup vs baseline: 1.4599x; 1.4599x over previous
#include <cuda_runtime.h>
#include <cuda_fp16.h>
#include <cstdint>
#include <cstddef>

#define V_   512
#define L_   13
#define NC   2048            // B*C = 64*32
#define ND   26624           // 13*NC dense column count (j = l*NC + nc)
#define NJ   6656            // V_*L_ dense (v,l) per batch image
#define COUT 64
#define KCAT 224
#define NB   64              // batch

// ------------------------- scratch (device globals; no allocs) -------------
__device__ __align__(16) __half g_Ah[6 * V_ * V_];           // [k][v][w] fp16
__device__ __align__(16) __half g_Xd[(size_t)V_ * ND];       // [v][l*NC+nc]
__device__ __align__(16) __half g_Yd[(size_t)6 * V_ * ND];   // [k][w][l*NC+nc]
__device__ __align__(16) __half g_Wt[KCAT * COUT];           // [kc][o]

// ------------------------- PTX helpers ------------------------------------
__device__ __forceinline__ uint32_t smem_u32(const void* p) {
    return (uint32_t)__cvta_generic_to_shared(p);
}
__device__ __forceinline__ void cpasync16(uint32_t dst, const void* src) {
    asm volatile("cp.async.cg.shared.global [%0], [%1], 16;\n" :: "r"(dst), "l"(src));
}
__device__ __forceinline__ void cpcommit() { asm volatile("cp.async.commit_group;\n" ::: "memory"); }
template <int N>
__device__ __forceinline__ void cpwait() { asm volatile("cp.async.wait_group %0;\n" :: "n"(N) : "memory"); }

// A fragment (row-major m16k16) from SMEM stored [k][m], via x4 .trans
__device__ __forceinline__ void ldmA(uint32_t a[4], uint32_t addr) {
    asm volatile("ldmatrix.sync.aligned.m8n8.x4.trans.shared.b16 {%0,%1,%2,%3}, [%4];\n"
                 : "=r"(a[0]), "=r"(a[1]), "=r"(a[2]), "=r"(a[3]) : "r"(addr));
}
// B fragment (col-major k16n8) from SMEM stored [k][n], via x2 .trans
__device__ __forceinline__ void ldmB(uint32_t b[2], uint32_t addr) {
    asm volatile("ldmatrix.sync.aligned.m8n8.x2.trans.shared.b16 {%0,%1}, [%2];\n"
                 : "=r"(b[0]), "=r"(b[1]) : "r"(addr));
}
// B fragment from SMEM stored [n][k] (B^T row-major), via x2 non-trans
__device__ __forceinline__ void ldmB_nt(uint32_t b[2], uint32_t addr) {
    asm volatile("ldmatrix.sync.aligned.m8n8.x2.shared.b16 {%0,%1}, [%2];\n"
                 : "=r"(b[0]), "=r"(b[1]) : "r"(addr));
}
__device__ __forceinline__ void mma16816(float c[4], const uint32_t a[4], const uint32_t b[2]) {
    asm volatile("mma.sync.aligned.m16n8k16.row.col.f32.f16.f16.f32 "
                 "{%0,%1,%2,%3}, {%4,%5,%6,%7}, {%8,%9}, {%0,%1,%2,%3};\n"
                 : "+f"(c[0]), "+f"(c[1]), "+f"(c[2]), "+f"(c[3])
                 : "r"(a[0]), "r"(a[1]), "r"(a[2]), "r"(a[3]), "r"(b[0]), "r"(b[1]));
}

// ------------------------- prep kernels ------------------------------------
// A_j @ A_j, fp32 accumulate, fp16 straight into g_Ah odd slots (layout [i][w])
__global__ __launch_bounds__(1024) void sq_kernel(const float* __restrict__ s0,
                                                  const float* __restrict__ s1,
                                                  const float* __restrict__ s2) {
    const float* A = (blockIdx.z == 0) ? s0 : (blockIdx.z == 1) ? s1 : s2;
    __half* O = g_Ah + (size_t)(2 * blockIdx.z + 1) * V_ * V_;
    __shared__ float a[32][33], bsh[32][33];
    int tx = threadIdx.x, ty = threadIdx.y;
    int i = blockIdx.y * 32 + ty;
    int w = blockIdx.x * 32 + tx;
    float acc = 0.f;
    for (int kt = 0; kt < 16; kt++) {
        a[ty][tx]   = A[i * V_ + kt * 32 + tx];
        bsh[ty][tx] = A[(kt * 32 + ty) * V_ + w];
        __syncthreads();
#pragma unroll
        for (int kk = 0; kk < 32; kk++) acc += a[ty][kk] * bsh[kk][tx];
        __syncthreads();
    }
    O[i * V_ + w] = __float2half(acc);
}

// fp32 -> fp16 copy of supports into even slots (float4 loads)
__global__ __launch_bounds__(256) void quant_A(const float* __restrict__ s0,
                                               const float* __restrict__ s1,
                                               const float* __restrict__ s2) {
    int i = blockIdx.x * 256 + threadIdx.x;   // over 65536 = (512*512)/4
    const float* srcs[3] = {s0, s1, s2};
#pragma unroll
    for (int j = 0; j < 3; j++) {
        float4 v = ((const float4*)srcs[j])[i];
        __half2* d = (__half2*)(g_Ah + (size_t)(2 * j) * V_ * V_ + (size_t)i * 4);
        d[0] = __floats2half2_rn(v.x, v.y);
        d[1] = __floats2half2_rn(v.z, v.w);
    }
}

// x[nc][j=v*13+l] fp32 -> g_Xd[v][l*NC+nc] fp16 via 32x32 smem transpose
__global__ __launch_bounds__(256) void repack_t(const float* __restrict__ x) {
    __shared__ float t[32][33];
    int jt = blockIdx.x * 32, nct = blockIdx.y * 32;
    int tx = threadIdx.x, ty = threadIdx.y;   // (32, 8)
#pragma unroll
    for (int r = ty; r < 32; r += 8)
        t[r][tx] = x[(size_t)(nct + r) * NJ + jt + tx];
    __syncthreads();
#pragma unroll
    for (int r = ty; r < 32; r += 8) {
        int j = jt + r;
        int v = j / 13, l = j - v * 13;
        g_Xd[(size_t)v * ND + l * NC + nct + tx] = __float2half(t[tx][r]);
    }
}

__global__ __launch_bounds__(256) void conv_W(const float* __restrict__ W) {
    int t = blockIdx.x * 256 + threadIdx.x;   // 14336 = 56*256
    int o = t / KCAT, kc = t % KCAT;
    g_Wt[kc * COUT + o] = __float2half(W[t]);
}

// ------------------------- GEMM 1: propagations (dense N) ------------------
// Yd_k[w][j] = sum_v P_k[v][w] * Xd[v][j],  M=512(w), K=512(v), N=26624 dense
// BM=128, BN=128, BK=32; 8 warps 2(M) x 4(N); warp tile 64x32
// 3-stage cp.async, single __syncthreads per k-tile, 2 CTAs/SM.
#define PROP_SA   (32 * 136)          // halfs, A tile per stage
#define PROP_SS   (2 * PROP_SA)       // halfs per stage (A + B)
#define PROP_SMEM (3 * PROP_SS * 2)   // 52224 bytes

__global__ void __launch_bounds__(256, 2) gemm_prop() {
    extern __shared__ __half sm[];
    int tid = threadIdx.x;
    int lane = tid & 31, wid = tid >> 5;
    int warp_m = wid >> 2;              // 0..1
    int warp_n = wid & 3;               // 0..3
    int w0 = blockIdx.y * 128;
    int j0 = blockIdx.x * 128;          // dense column base
    int k6 = blockIdx.z;
    const __half* Abase = g_Ah + (size_t)k6 * V_ * V_;

    auto load_tiles = [&](int kt, int s) {
        __half* As = sm + s * PROP_SS;
        __half* Bs = As + PROP_SA;
        int v0 = kt * 32;
#pragma unroll
        for (int i = 0; i < 2; i++) {
            int ch = tid + i * 256;                 // 512 chunks of 16B
            int r = ch >> 4, c16 = ch & 15;
            cpasync16(smem_u32(As + r * 136 + c16 * 8),
                      Abase + (size_t)(v0 + r) * V_ + w0 + c16 * 8);
        }
#pragma unroll
        for (int i = 0; i < 2; i++) {
            int ch = tid + i * 256;                 // B rows fully contiguous
            int r = ch >> 4, c16 = ch & 15;
            cpasync16(smem_u32(Bs + r * 136 + c16 * 8),
                      g_Xd + (size_t)(v0 + r) * ND + j0 + c16 * 8);
        }
    };

    float acc[4][4][4] = {};

    load_tiles(0, 0); cpcommit();
    load_tiles(1, 1); cpcommit();

    for (int kt = 0; kt < 16; kt++) {
        cpwait<1>();
        __syncthreads();                 // tile kt resident; all warps done with kt-1
        if (kt + 2 < 16) load_tiles(kt + 2, (kt + 2) % 3);
        cpcommit();
        __half* As = sm + (kt % 3) * PROP_SS;
        __half* Bs = As + PROP_SA;
#pragma unroll
        for (int ks = 0; ks < 2; ks++) {
            uint32_t af[4][4], bf[4][2];
            int arow = ks * 16 + (lane & 7) + ((lane & 16) >> 1);
            int acolb = warp_m * 64 + (lane & 8);
#pragma unroll
            for (int mt = 0; mt < 4; mt++)
                ldmA(af[mt], smem_u32(As + arow * 136 + acolb + mt * 16));
            int brow = ks * 16 + (lane & 15);
            int bcolb = warp_n * 32;
#pragma unroll
            for (int nt = 0; nt < 4; nt++)
                ldmB(bf[nt], smem_u32(Bs + brow * 136 + bcolb + nt * 8));
#pragma unroll
            for (int mt = 0; mt < 4; mt++)
#pragma unroll
                for (int nt = 0; nt < 4; nt++)
                    mma16816(acc[mt][nt], af[mt], bf[nt]);
        }
    }

    // epilogue: dense Yd, contiguous half2 stores
    int g = lane >> 2, t4 = lane & 3;
    __half* Ybase = g_Yd + (size_t)k6 * V_ * ND;
#pragma unroll
    for (int mt = 0; mt < 4; mt++) {
        int w = w0 + warp_m * 64 + mt * 16 + g;
        __half* row0 = Ybase + (size_t)w * ND;
        __half* row1 = row0 + (size_t)8 * ND;
#pragma unroll
        for (int nt = 0; nt < 4; nt++) {
            int j = j0 + warp_n * 32 + nt * 8 + 2 * t4;
            *(__half2*)(row0 + j) = __floats2half2_rn(acc[mt][nt][0], acc[mt][nt][1]);
            *(__half2*)(row1 + j) = __floats2half2_rn(acc[mt][nt][2], acc[mt][nt][3]);
        }
    }
}

// ------------------------- GEMM 2: 1x1 conv, fully dense -------------------
// out[n][o][j=(v,l)] = b[o] + sum_kc Wt[kc][o] * H[kc][j]
// M=64(o), K=224, N=6656 per n = 52 tiles of 128 dense cols.
// B-tiles gathered from Yd/Xd: col (v,l) -> 64B contiguous 32 channels.
// Bt smem stored [col][k] -> non-trans ldmatrix. 3-stage, 2 CTAs/SM.
#define OB_ROW 40   // halfs per Bt row (32 k + 8 pad -> 80B, odd multiple of 16B)

__global__ void __launch_bounds__(256, 2) gemm_out(const float* __restrict__ bias,
                                                   float* __restrict__ out) {
    __shared__ __half Ws[3][32][72];        // [k][o], 144B rows
    __shared__ __half Bt[3][128][OB_ROW];   // [col][k], 80B rows
    int tid = threadIdx.x;
    int lane = tid & 31, wid = tid >> 5;
    int warp_m = wid >> 2;              // 0..1 (32 o each)
    int warp_n = wid & 3;               // 0..3 (32 cols each)
    int n   = blockIdx.y;
    int jt0 = blockIdx.x * 128;         // dense (v,l) base

    auto load_tiles = [&](int kb, int s) {
        {   // W: 32 rows x 64 halfs = 256 chunks
            int r = tid >> 3, c16 = tid & 7;
            cpasync16(smem_u32(&Ws[s][r][c16 * 8]),
                      g_Wt + (size_t)(kb * 32 + r) * COUT + c16 * 8);
        }
        // B: 128 cols x 4 chunks = 512 chunks
        const __half* src_base = (kb == 0) ? g_Xd
                               : g_Yd + (size_t)(kb - 1) * V_ * ND;
#pragma unroll
        for (int i = 0; i < 2; i++) {
            int id = tid + i * 256;
            int col = id >> 2, q = id & 3;
            int j = jt0 + col;
            int v = j / 13, l = j - v * 13;
            cpasync16(smem_u32(&Bt[s][col][q * 8]),
                      src_base + (size_t)v * ND + l * NC + n * 32 + q * 8);
        }
    };

    float acc[2][4][4] = {};

    load_tiles(0, 0); cpcommit();
    load_tiles(1, 1); cpcommit();

    for (int kb = 0; kb < 7; kb++) {
        cpwait<1>();
        __syncthreads();
        if (kb + 2 < 7) load_tiles(kb + 2, (kb + 2) % 3);
        cpcommit();
        int s = kb % 3;
#pragma unroll
        for (int ks = 0; ks < 2; ks++) {
            uint32_t af[2][4], bf[4][2];
            int arow = ks * 16 + (lane & 7) + ((lane & 16) >> 1);
            int acolb = warp_m * 32 + (lane & 8);
#pragma unroll
            for (int mt = 0; mt < 2; mt++)
                ldmA(af[mt], smem_u32(&Ws[s][arow][acolb + mt * 16]));
            int bn = warp_n * 32 + (lane & 7);
            int bk = ks * 16 + (lane & 8);
#pragma unroll
            for (int nt = 0; nt < 4; nt++)
                ldmB_nt(bf[nt], smem_u32(&Bt[s][bn + nt * 8][bk]));
#pragma unroll
            for (int mt = 0; mt < 2; mt++)
#pragma unroll
                for (int nt = 0; nt < 4; nt++)
                    mma16816(acc[mt][nt], af[mt], bf[nt]);
        }
    }

    // epilogue: +bias, contiguous float2 stores (out is dense in (v,l))
    int g = lane >> 2, t = lane & 3;
#pragma unroll
    for (int mt = 0; mt < 2; mt++) {
        int o = warp_m * 32 + mt * 16 + g;
        float b0 = bias[o], b1 = bias[o + 8];
        float* row0 = out + ((size_t)n * COUT + o) * NJ;
        float* row1 = row0 + (size_t)8 * NJ;
#pragma unroll
        for (int nt = 0; nt < 4; nt++) {
            int j = jt0 + warp_n * 32 + nt * 8 + 2 * t;
            *(float2*)(row0 + j) = make_float2(acc[mt][nt][0] + b0, acc[mt][nt][1] + b0);
            *(float2*)(row1 + j) = make_float2(acc[mt][nt][2] + b1, acc[mt][nt][3] + b1);
        }
    }
}

// ------------------------- launch ------------------------------------------
extern "C" void kernel_launch(void* const* d_in, const int* in_sizes, int n_in,
                              void* d_out, int out_size) {
    const float* x  = (const float*)d_in[0];
    const float* s0 = (const float*)d_in[1];
    const float* s1 = (const float*)d_in[2];
    const float* s2 = (const float*)d_in[3];
    const float* W  = (const float*)d_in[4];
    const float* b  = (const float*)d_in[5];
    float* out = (float*)d_out;
    (void)in_sizes; (void)n_in; (void)out_size;

    static bool attr_done = false;
    if (!attr_done) {
        cudaFuncSetAttribute(gemm_prop, cudaFuncAttributeMaxDynamicSharedMemorySize, PROP_SMEM);
        attr_done = true;
    }

    sq_kernel<<<dim3(16, 16, 3), dim3(32, 32)>>>(s0, s1, s2);
    quant_A<<<256, 256>>>(s0, s1, s2);
    repack_t<<<dim3(208, 64), dim3(32, 8)>>>(x);
    conv_W<<<56, 256>>>(W);
    gemm_prop<<<dim3(208, 4, 6), 256, PROP_SMEM>>>();
    gemm_out<<<dim3(52, 64), 256>>>(b, out);
}